// round 1
// baseline (speedup 1.0000x reference)
#include <cuda_runtime.h>

#define L 2048
#define E 128
#define H 8
#define NITEMS 50000
#define WAM 5

// ---------------- scratch (device globals; no allocation allowed) ----------------
__device__ float g_I[E * L];        // I = I_w + I_q, [E][L]
__device__ float g_q[H * E * L];    // [1024][2048]
__device__ float g_k[H * E * L];
__device__ float g_v[H * E * L];
__device__ float g_b[H * E * L];    // attention output, [1024][2048]
__device__ float g_o[E * L];        // Head_agg output, [128][2048]

// ---------------- kernel 1: gather + build I; also writes I_q.T and init row ----
__global__ void build_I_kernel(const int* __restrict__ sq, const int* __restrict__ cq,
                               const float* __restrict__ item, const float* __restrict__ uinit,
                               const float* __restrict__ wrep, float* __restrict__ out) {
    int l = blockIdx.x;      // 0..2047
    int e = threadIdx.x;     // 0..127
    int s = sq[l], c = cq[l];
    float iq = item[e * NITEMS + s];
    float iw = wrep[e * WAM + c];
    g_I[e * L + l] = iq + iw;
    // output region 1: I_q.T (row-major [L][E]) at offset E*L
    out[E * L + l * E + e] = iq;
    // output region 0 row 0: user_init_representation
    if (l == 0) out[e] = uinit[e];
}

// ---------------- generic tiled fp32 GEMM: C[M][N] = A[M][K] * B[K][N] ----------
// BM=64, BN=64, BK=32, 256 threads, 4x4 microtile
__global__ void gemm64(const float* __restrict__ A, const float* __restrict__ B,
                       float* __restrict__ C, int M, int N, int K) {
    __shared__ float As[64][36];   // padded (36 % 4 == 0 keeps float4 STS aligned)
    __shared__ float Bs[32][64];
    int tid = threadIdx.x;
    int tx = tid & 15, ty = tid >> 4;
    int m0 = blockIdx.y * 64, n0 = blockIdx.x * 64;
    float acc[4][4] = {};

    for (int k0 = 0; k0 < K; k0 += 32) {
#pragma unroll
        for (int t = 0; t < 2; t++) {
            int idx = tid + t * 256;
            // A tile: 64 rows x 32 cols
            int r = idx >> 3, c4 = (idx & 7) << 2;
            float4 va = *(const float4*)&A[(m0 + r) * K + k0 + c4];
            *(float4*)&As[r][c4] = va;
            // B tile: 32 rows x 64 cols
            int rb = idx >> 4, cb = (idx & 15) << 2;
            float4 vb = *(const float4*)&B[(k0 + rb) * N + n0 + cb];
            *(float4*)&Bs[rb][cb] = vb;
        }
        __syncthreads();
#pragma unroll
        for (int kk = 0; kk < 32; kk++) {
            float a0 = As[ty * 4 + 0][kk];
            float a1 = As[ty * 4 + 1][kk];
            float a2 = As[ty * 4 + 2][kk];
            float a3 = As[ty * 4 + 3][kk];
            float4 b4 = *(float4*)&Bs[kk][tx * 4];
            acc[0][0] += a0 * b4.x; acc[0][1] += a0 * b4.y; acc[0][2] += a0 * b4.z; acc[0][3] += a0 * b4.w;
            acc[1][0] += a1 * b4.x; acc[1][1] += a1 * b4.y; acc[1][2] += a1 * b4.z; acc[1][3] += a1 * b4.w;
            acc[2][0] += a2 * b4.x; acc[2][1] += a2 * b4.y; acc[2][2] += a2 * b4.z; acc[2][3] += a2 * b4.w;
            acc[3][0] += a3 * b4.x; acc[3][1] += a3 * b4.y; acc[3][2] += a3 * b4.z; acc[3][3] += a3 * b4.w;
        }
        __syncthreads();
    }
#pragma unroll
    for (int i = 0; i < 4; i++) {
        float4 v = make_float4(acc[i][0], acc[i][1], acc[i][2], acc[i][3]);
        *(float4*)&C[(m0 + ty * 4 + i) * N + n0 + tx * 4] = v;
    }
}

// ---------------- flash attention, fp32, BQ=BK=64, online softmax ---------------
// grid (L/64=32, H=8), 256 threads.  Tiles stored [e][col] (64-wide rows).
// smem: Qs 32K + Ks 32K + Vs 32K + Ps 16K + red 1K + m/l/sc 0.75K  ≈ 114 KB
#define FL_SMEM ((3 * E * 64 + 64 * 64 + 4 * 64 + 3 * 64) * 4)

__global__ void flash_kernel() {
    extern __shared__ float sm[];
    float* Qs  = sm;                    // [128][64]
    float* Ks  = Qs + E * 64;           // [128][64]
    float* Vs  = Ks + E * 64;           // [128][64]
    float* Ps  = Vs + E * 64;           // [64][64]
    float* red = Ps + 64 * 64;          // [4][64]
    float* m_s = red + 4 * 64;          // [64]
    float* l_s = m_s + 64;              // [64]
    float* sc_s = l_s + 64;             // [64]

    const float RED = 0.08838834764831845f;   // 1/sqrt(128)
    const float NEG = -1e30f;

    int tid = threadIdx.x;
    int tx = tid & 15, ty = tid >> 4;
    int h = blockIdx.y;
    int jb = blockIdx.x;
    int j0 = jb * 64;

    // load Q tile: Qs[e][j] = q[h*128+e][j0+j]
#pragma unroll
    for (int t = 0; t < 8; t++) {
        int idx = tid + t * 256;            // 2048 float4
        int e = idx >> 4, j4 = (idx & 15) << 2;
        *(float4*)&Qs[e * 64 + j4] = *(const float4*)&g_q[(h * E + e) * L + j0 + j4];
    }
    if (tid < 64) { m_s[tid] = NEG; l_s[tid] = 0.0f; }

    float acc[8][4] = {};   // e-rows ty*8..+7, j-cols tx*4..+3
    __syncthreads();

    for (int kb = 0; kb <= jb; kb++) {
        int i0 = kb * 64;
        // load K, V tiles
#pragma unroll
        for (int t = 0; t < 8; t++) {
            int idx = tid + t * 256;
            int e = idx >> 4, i4 = (idx & 15) << 2;
            *(float4*)&Ks[e * 64 + i4] = *(const float4*)&g_k[(h * E + e) * L + i0 + i4];
            *(float4*)&Vs[e * 64 + i4] = *(const float4*)&g_v[(h * E + e) * L + i0 + i4];
        }
        __syncthreads();

        // S[i][j] = sum_e K[e][i] * Q[e][j];  i-rows ty*4..+3, j-cols tx*4..+3
        float s[4][4] = {};
#pragma unroll 4
        for (int e = 0; e < E; e++) {
            float4 kv = *(float4*)&Ks[e * 64 + ty * 4];
            float4 qv = *(float4*)&Qs[e * 64 + tx * 4];
            s[0][0] += kv.x * qv.x; s[0][1] += kv.x * qv.y; s[0][2] += kv.x * qv.z; s[0][3] += kv.x * qv.w;
            s[1][0] += kv.y * qv.x; s[1][1] += kv.y * qv.y; s[1][2] += kv.y * qv.z; s[1][3] += kv.y * qv.w;
            s[2][0] += kv.z * qv.x; s[2][1] += kv.z * qv.y; s[2][2] += kv.z * qv.z; s[2][3] += kv.z * qv.w;
            s[3][0] += kv.w * qv.x; s[3][1] += kv.w * qv.y; s[3][2] += kv.w * qv.z; s[3][3] += kv.w * qv.w;
        }
        bool diag = (kb == jb);
#pragma unroll
        for (int ii = 0; ii < 4; ii++)
#pragma unroll
            for (int jj = 0; jj < 4; jj++) {
                float val = s[ii][jj] * RED;
                if (diag && (ty * 4 + ii) > (tx * 4 + jj)) val = NEG;  // causal: keep i <= j
                Ps[(ty * 4 + ii) * 64 + tx * 4 + jj] = val;
            }
        __syncthreads();

        // column-wise max (4 threads per column)
        {
            int j = tid & 63, q = tid >> 6;
            float pm = NEG;
#pragma unroll
            for (int r = 0; r < 16; r++) pm = fmaxf(pm, Ps[(q * 16 + r) * 64 + j]);
            red[q * 64 + j] = pm;
        }
        __syncthreads();
        if (tid < 64) {
            int j = tid;
            float newm = fmaxf(fmaxf(red[j], red[64 + j]), fmaxf(red[128 + j], red[192 + j]));
            newm = fmaxf(newm, m_s[j]);
            sc_s[j] = __expf(m_s[j] - newm);
            m_s[j] = newm;
        }
        __syncthreads();

        // exponentiate + partial sums
        {
            int j = tid & 63, q = tid >> 6;
            float mj = m_s[j];
            float ps = 0.0f;
#pragma unroll
            for (int r = 0; r < 16; r++) {
                float p = __expf(Ps[(q * 16 + r) * 64 + j] - mj);
                Ps[(q * 16 + r) * 64 + j] = p;
                ps += p;
            }
            red[q * 64 + j] = ps;
        }
        __syncthreads();
        if (tid < 64) {
            int j = tid;
            l_s[j] = l_s[j] * sc_s[j] + (red[j] + red[64 + j] + red[128 + j] + red[192 + j]);
        }

        // rescale accumulator, then acc[e][j] += sum_i V[e][i] * P[i][j]
        float scl0 = sc_s[tx * 4 + 0], scl1 = sc_s[tx * 4 + 1],
              scl2 = sc_s[tx * 4 + 2], scl3 = sc_s[tx * 4 + 3];
#pragma unroll
        for (int r = 0; r < 8; r++) {
            acc[r][0] *= scl0; acc[r][1] *= scl1; acc[r][2] *= scl2; acc[r][3] *= scl3;
        }
#pragma unroll 2
        for (int i = 0; i < 64; i += 4) {
            float4 p0 = *(float4*)&Ps[(i + 0) * 64 + tx * 4];
            float4 p1 = *(float4*)&Ps[(i + 1) * 64 + tx * 4];
            float4 p2 = *(float4*)&Ps[(i + 2) * 64 + tx * 4];
            float4 p3 = *(float4*)&Ps[(i + 3) * 64 + tx * 4];
#pragma unroll
            for (int r = 0; r < 8; r++) {
                float4 v4 = *(float4*)&Vs[(ty * 8 + r) * 64 + i];
                acc[r][0] += v4.x * p0.x + v4.y * p1.x + v4.z * p2.x + v4.w * p3.x;
                acc[r][1] += v4.x * p0.y + v4.y * p1.y + v4.z * p2.y + v4.w * p3.y;
                acc[r][2] += v4.x * p0.z + v4.y * p1.z + v4.z * p2.z + v4.w * p3.z;
                acc[r][3] += v4.x * p0.w + v4.y * p1.w + v4.z * p2.w + v4.w * p3.w;
            }
        }
        __syncthreads();
    }

    // finalize: divide by l and store b
    float inv0 = 1.0f / l_s[tx * 4 + 0], inv1 = 1.0f / l_s[tx * 4 + 1],
          inv2 = 1.0f / l_s[tx * 4 + 2], inv3 = 1.0f / l_s[tx * 4 + 3];
#pragma unroll
    for (int r = 0; r < 8; r++) {
        float4 v = make_float4(acc[r][0] * inv0, acc[r][1] * inv1,
                               acc[r][2] * inv2, acc[r][3] * inv3);
        *(float4*)&g_b[(h * E + ty * 8 + r) * L + j0 + tx * 4] = v;
    }
}

// ---------------- output assembly: o.T into u_state rows 1.., last row separate --
__global__ void assemble_kernel(float* __restrict__ out) {
    int idx = blockIdx.x * blockDim.x + threadIdx.x;  // 0 .. 128*2048-1
    int j = idx >> 7, e = idx & 127;
    float v = g_o[e * L + j];
    if (j < L - 1) out[(j + 1) * E + e] = v;          // u_state rows 1..2047
    else out[2 * E * L + e] = v;                      // u_state[-1]
}

// ---------------- launch ----------------
extern "C" void kernel_launch(void* const* d_in, const int* in_sizes, int n_in,
                              void* d_out, int out_size) {
    const int*   sq    = (const int*)d_in[0];
    const int*   cq    = (const int*)d_in[1];
    const float* item  = (const float*)d_in[2];
    const float* uinit = (const float*)d_in[3];
    const float* wrep  = (const float*)d_in[4];
    const float* Wq    = (const float*)d_in[5];
    const float* Wk    = (const float*)d_in[6];
    const float* Wv    = (const float*)d_in[7];
    const float* Hagg  = (const float*)d_in[8];
    float* out = (float*)d_out;

    float *pI, *pq, *pk, *pv, *pb, *po;
    cudaGetSymbolAddress((void**)&pI, g_I);
    cudaGetSymbolAddress((void**)&pq, g_q);
    cudaGetSymbolAddress((void**)&pk, g_k);
    cudaGetSymbolAddress((void**)&pv, g_v);
    cudaGetSymbolAddress((void**)&pb, g_b);
    cudaGetSymbolAddress((void**)&po, g_o);

    build_I_kernel<<<L, E>>>(sq, cq, item, uinit, wrep, out);

    dim3 gQKV(L / 64, (H * E) / 64);                 // (32, 16)
    gemm64<<<gQKV, 256>>>(Wq, pI, pq, H * E, L, E);
    gemm64<<<gQKV, 256>>>(Wk, pI, pk, H * E, L, E);
    gemm64<<<gQKV, 256>>>(Wv, pI, pv, H * E, L, E);

    cudaFuncSetAttribute(flash_kernel, cudaFuncAttributeMaxDynamicSharedMemorySize, FL_SMEM);
    flash_kernel<<<dim3(L / 64, H), 256, FL_SMEM>>>();

    gemm64<<<dim3(L / 64, E / 64), 256>>>(Hagg, pb, po, E, L, H * E);  // (32, 2)

    assemble_kernel<<<(E * L) / 256, 256>>>(out);
}